// round 10
// baseline (speedup 1.0000x reference)
#include <cuda_runtime.h>
#include <cstdint>

#define MAXN 100000
#define MAXE 800000
#define H 64
#define SCAN_PAD (MAXN + 2048)

// ---------------- device scratch ----------------
__device__ float g_xenc[MAXN * H];
__device__ float g_h[MAXN * H];
__device__ float g_x1[MAXN * H];
__device__ float g_x2[MAXN * H];
__device__ float g_res[MAXN * H];
__device__ float g_tw[1000 * H];
__device__ float g_dinv[MAXN];
__device__ float g_nf[MAXN * 4 * H];

__device__ int  g_deg[2 * MAXN];
__device__ int  g_offD[SCAN_PAD];
__device__ int  g_offS[SCAN_PAD];
__device__ int  g_curD[MAXN];
__device__ int  g_curS[MAXN];
__device__ int  g_bsum[256];
__device__ int  g_srcD[MAXE];
__device__ int4 g_epk[MAXE];   // {e, dst, ts, 0} permuted by src

// ---------------- histogram ----------------
__global__ void k_hist(const int* __restrict__ src, const int* __restrict__ dst,
                       int* __restrict__ indeg, int* __restrict__ outdeg, int E) {
    int i = blockIdx.x * blockDim.x + threadIdx.x;
    if (i < E) {
        atomicAdd(&indeg[dst[i]], 1);
        atomicAdd(&outdeg[src[i]], 1);
    }
}

// ---------------- exclusive scan, two arrays at once (gridDim.y=2) ----------------
__global__ void k_scan_blk(const int* __restrict__ indeg, const int* __restrict__ outdeg,
                           int* __restrict__ offD, int* __restrict__ offS,
                           float* __restrict__ dinv, int* __restrict__ bsum, int n) {
    __shared__ int sm[1024];
    int y = blockIdx.y;
    const int* in = y ? outdeg : indeg;
    int* out = y ? offS : offD;
    int tid = threadIdx.x;
    int i = blockIdx.x * 1024 + tid;
    int v = (i < n) ? in[i] : 0;
    if (y == 0 && i < n) dinv[i] = rsqrtf((float)v + 1.0f);
    sm[tid] = v;
    __syncthreads();
#pragma unroll
    for (int off = 1; off < 1024; off <<= 1) {
        int t = (tid >= off) ? sm[tid - off] : 0;
        __syncthreads();
        sm[tid] += t;
        __syncthreads();
    }
    out[i] = sm[tid] - v;  // exclusive
    if (tid == 1023) bsum[y * 128 + blockIdx.x] = sm[1023];
}

__global__ void k_scan_top(int* __restrict__ bsum, int nb) {
    __shared__ int sm[128];
    int y = blockIdx.y;
    int tid = threadIdx.x;
    int v = (tid < nb) ? bsum[y * 128 + tid] : 0;
    sm[tid] = v;
    __syncthreads();
#pragma unroll
    for (int off = 1; off < 128; off <<= 1) {
        int t = (tid >= off) ? sm[tid - off] : 0;
        __syncthreads();
        sm[tid] += t;
        __syncthreads();
    }
    if (tid < nb) bsum[y * 128 + tid] = sm[tid] - v;
}

__global__ void k_scan_add(int* __restrict__ offD, int* __restrict__ offS,
                           int* __restrict__ curD, int* __restrict__ curS,
                           const int* __restrict__ bsum, int n) {
    int y = blockIdx.y;
    int* out = y ? offS : offD;
    int* cur = y ? curS : curD;
    int i = blockIdx.x * 1024 + threadIdx.x;
    int v = out[i] + bsum[y * 128 + blockIdx.x];
    out[i] = v;
    if (i < n) cur[i] = v;
}

// ---------------- permute edges into CSR order ----------------
__global__ void k_scatter_ids(const int* __restrict__ src, const int* __restrict__ dst,
                              const int* __restrict__ ts,
                              int* __restrict__ curD, int* __restrict__ curS,
                              int* __restrict__ srcD, int4* __restrict__ epk, int E) {
    int e = blockIdx.x * blockDim.x + threadIdx.x;
    if (e >= E) return;
    int s = src[e], d = dst[e];
    int p = atomicAdd(&curD[d], 1);
    srcD[p] = s;
    int q = atomicAdd(&curS[s], 1);
    epk[q] = make_int4(e, d, min(max(ts[e], 0), 999), 0);
}

// ---------------- time table ----------------
__global__ void k_ttable(const float* __restrict__ Temb, const float* __restrict__ Wt,
                         const float* __restrict__ bt, float* __restrict__ tw) {
    __shared__ float er[H];
    int t = blockIdx.x;
    int c = threadIdx.x;
    er[c] = Temb[t * H + c];
    __syncthreads();
    float a = bt[c];
#pragma unroll
    for (int k = 0; k < H; k++) a += er[k] * Wt[k * H + c];
    tw[t * H + c] = fmaxf(a, 0.0f);
}

// ---------------- tiled SGEMM: [M,K] @ [K,64], BM=256, 8x8 micro-tile ----------------
template <int K, bool RELU>
__global__ __launch_bounds__(256)
void k_gemm(const float* __restrict__ A, const float* __restrict__ W,
            const float* __restrict__ bias, const float* __restrict__ rowscale,
            float* __restrict__ C, int M) {
    __shared__ float As[16][260];   // transposed A tile (256 rows), 1040B row pitch
    __shared__ float Bs[16][64];
    __shared__ float bsm[64];

    const int tid = threadIdx.x;
    const int tx = tid & 7;         // col group: cols tx*8 .. tx*8+7
    const int ty = tid >> 3;        // row group: rows ty*8 .. ty*8+7
    const int m0 = blockIdx.x * 256;

    if (tid < 64) bsm[tid] = bias ? bias[tid] : 0.0f;

    float acc[8][8];
#pragma unroll
    for (int i = 0; i < 8; i++)
#pragma unroll
        for (int j = 0; j < 8; j++) acc[i][j] = 0.0f;

    for (int kc = 0; kc < K; kc += 16) {
        __syncthreads();
        // A tile: 256 rows x 16 k = 1024 float4
#pragma unroll
        for (int f = tid; f < 1024; f += 256) {
            int row = f >> 2, kq = f & 3;
            int gr = m0 + row;
            float4 v = make_float4(0.f, 0.f, 0.f, 0.f);
            if (gr < M) v = *(const float4*)(A + (size_t)gr * K + kc + kq * 4);
            As[kq * 4 + 0][row] = v.x;
            As[kq * 4 + 1][row] = v.y;
            As[kq * 4 + 2][row] = v.z;
            As[kq * 4 + 3][row] = v.w;
        }
        // B tile: 16x64 = 256 float4
        {
            int krow = tid >> 4, cq = tid & 15;
            *(float4*)&Bs[krow][cq * 4] = *(const float4*)(W + (size_t)(kc + krow) * 64 + cq * 4);
        }
        __syncthreads();
#pragma unroll
        for (int kk = 0; kk < 16; kk++) {
            float af[8], bf[8];
            *(float4*)&af[0] = *(const float4*)&As[kk][ty * 8];
            *(float4*)&af[4] = *(const float4*)&As[kk][ty * 8 + 4];
            *(float4*)&bf[0] = *(const float4*)&Bs[kk][tx * 8];
            *(float4*)&bf[4] = *(const float4*)&Bs[kk][tx * 8 + 4];
#pragma unroll
            for (int i = 0; i < 8; i++)
#pragma unroll
                for (int j = 0; j < 8; j++)
                    acc[i][j] = fmaf(af[i], bf[j], acc[i][j]);
        }
    }

#pragma unroll
    for (int i = 0; i < 8; i++) {
        int row = m0 + ty * 8 + i;
        if (row < M) {
            float sc = rowscale ? rowscale[row] : 1.0f;
            float4 v0, v1;
            v0.x = acc[i][0] + bsm[tx * 8 + 0];
            v0.y = acc[i][1] + bsm[tx * 8 + 1];
            v0.z = acc[i][2] + bsm[tx * 8 + 2];
            v0.w = acc[i][3] + bsm[tx * 8 + 3];
            v1.x = acc[i][4] + bsm[tx * 8 + 4];
            v1.y = acc[i][5] + bsm[tx * 8 + 5];
            v1.z = acc[i][6] + bsm[tx * 8 + 6];
            v1.w = acc[i][7] + bsm[tx * 8 + 7];
            if (RELU) {
                v0.x = fmaxf(v0.x, 0.f); v0.y = fmaxf(v0.y, 0.f);
                v0.z = fmaxf(v0.z, 0.f); v0.w = fmaxf(v0.w, 0.f);
                v1.x = fmaxf(v1.x, 0.f); v1.y = fmaxf(v1.y, 0.f);
                v1.z = fmaxf(v1.z, 0.f); v1.w = fmaxf(v1.w, 0.f);
            }
            v0.x *= sc; v0.y *= sc; v0.z *= sc; v0.w *= sc;
            v1.x *= sc; v1.y *= sc; v1.z *= sc; v1.w *= sc;
            *(float4*)(C + (size_t)row * 64 + tx * 8) = v0;
            *(float4*)(C + (size_t)row * 64 + tx * 8 + 4) = v1;
        }
    }
}

// ---------------- dual SGEMM: H = (A@W1)*dinv[row], R = A@W2 + b2  (K=64) --------
__global__ __launch_bounds__(256)
void k_gemm_dual(const float* __restrict__ A, const float* __restrict__ W1,
                 const float* __restrict__ W2, const float* __restrict__ b2,
                 const float* __restrict__ dinv, float* __restrict__ Hh,
                 float* __restrict__ R, int M) {
    __shared__ float As[16][132];
    __shared__ float Bs[16][128];
    __shared__ float bsm[64];

    const int tid = threadIdx.x;
    const int tx = tid & 15;
    const int ty = tid >> 4;
    const int m0 = blockIdx.x * 128;

    if (tid < 64) bsm[tid] = b2[tid];

    float acc[8][8];
#pragma unroll
    for (int i = 0; i < 8; i++)
#pragma unroll
        for (int j = 0; j < 8; j++) acc[i][j] = 0.0f;

    for (int kc = 0; kc < 64; kc += 16) {
        __syncthreads();
#pragma unroll
        for (int f = tid; f < 512; f += 256) {
            int row = f >> 2, kq = f & 3;
            int gr = m0 + row;
            float4 v = make_float4(0.f, 0.f, 0.f, 0.f);
            if (gr < M) v = *(const float4*)(A + (size_t)gr * 64 + kc + kq * 4);
            As[kq * 4 + 0][row] = v.x;
            As[kq * 4 + 1][row] = v.y;
            As[kq * 4 + 2][row] = v.z;
            As[kq * 4 + 3][row] = v.w;
        }
#pragma unroll
        for (int f = tid; f < 512; f += 256) {
            int krow = f >> 5, cq = f & 31;
            float4 v = (cq < 16)
                ? *(const float4*)(W1 + (size_t)(kc + krow) * 64 + cq * 4)
                : *(const float4*)(W2 + (size_t)(kc + krow) * 64 + (cq - 16) * 4);
            *(float4*)&Bs[krow][cq * 4] = v;
        }
        __syncthreads();
#pragma unroll
        for (int kk = 0; kk < 16; kk++) {
            float af[8], bf[8];
            *(float4*)&af[0] = *(const float4*)&As[kk][ty * 8];
            *(float4*)&af[4] = *(const float4*)&As[kk][ty * 8 + 4];
            *(float4*)&bf[0] = *(const float4*)&Bs[kk][tx * 8];
            *(float4*)&bf[4] = *(const float4*)&Bs[kk][tx * 8 + 4];
#pragma unroll
            for (int i = 0; i < 8; i++)
#pragma unroll
                for (int j = 0; j < 8; j++)
                    acc[i][j] = fmaf(af[i], bf[j], acc[i][j]);
        }
    }

    const bool second = (tx >= 8);
    const int c0 = second ? (tx - 8) * 8 : tx * 8;
#pragma unroll
    for (int i = 0; i < 8; i++) {
        int row = m0 + ty * 8 + i;
        if (row < M) {
            if (!second) {
                float sc = dinv[row];
                float4 v0, v1;
                v0.x = acc[i][0] * sc; v0.y = acc[i][1] * sc;
                v0.z = acc[i][2] * sc; v0.w = acc[i][3] * sc;
                v1.x = acc[i][4] * sc; v1.y = acc[i][5] * sc;
                v1.z = acc[i][6] * sc; v1.w = acc[i][7] * sc;
                *(float4*)(Hh + (size_t)row * 64 + c0) = v0;
                *(float4*)(Hh + (size_t)row * 64 + c0 + 4) = v1;
            } else {
                float4 v0, v1;
                v0.x = acc[i][0] + bsm[c0 + 0]; v0.y = acc[i][1] + bsm[c0 + 1];
                v0.z = acc[i][2] + bsm[c0 + 2]; v0.w = acc[i][3] + bsm[c0 + 3];
                v1.x = acc[i][4] + bsm[c0 + 4]; v1.y = acc[i][5] + bsm[c0 + 5];
                v1.z = acc[i][6] + bsm[c0 + 6]; v1.w = acc[i][7] + bsm[c0 + 7];
                *(float4*)(R + (size_t)row * 64 + c0) = v0;
                *(float4*)(R + (size_t)row * 64 + c0 + 4) = v1;
            }
        }
    }
}

// ---------------- classifier: BM=256, 8x8; projection in registers + shfl reduce ----
__global__ __launch_bounds__(256)
void k_gemm_cls(const float* __restrict__ A, const float* __restrict__ W,
                const float* __restrict__ bias, const float* __restrict__ Wm2,
                const float* __restrict__ bm2, float* __restrict__ out, int M) {
    __shared__ float As[16][260];
    __shared__ float Bs[16][64];
    __shared__ float bsm[64];
    __shared__ float wm2s[128];
    __shared__ float bm2s[2];

    const int tid = threadIdx.x;
    const int tx = tid & 7;
    const int ty = tid >> 3;
    const int m0 = blockIdx.x * 256;

    if (tid < 64) bsm[tid] = bias[tid];
    if (tid < 128) wm2s[tid] = Wm2[tid];
    if (tid < 2) bm2s[tid] = bm2[tid];

    float acc[8][8];
#pragma unroll
    for (int i = 0; i < 8; i++)
#pragma unroll
        for (int j = 0; j < 8; j++) acc[i][j] = 0.0f;

    for (int kc = 0; kc < 256; kc += 16) {
        __syncthreads();
#pragma unroll
        for (int f = tid; f < 1024; f += 256) {
            int row = f >> 2, kq = f & 3;
            int gr = m0 + row;
            float4 v = make_float4(0.f, 0.f, 0.f, 0.f);
            if (gr < M) v = *(const float4*)(A + (size_t)gr * 256 + kc + kq * 4);
            As[kq * 4 + 0][row] = v.x;
            As[kq * 4 + 1][row] = v.y;
            As[kq * 4 + 2][row] = v.z;
            As[kq * 4 + 3][row] = v.w;
        }
        {
            int krow = tid >> 4, cq = tid & 15;
            *(float4*)&Bs[krow][cq * 4] = *(const float4*)(W + (size_t)(kc + krow) * 64 + cq * 4);
        }
        __syncthreads();
#pragma unroll
        for (int kk = 0; kk < 16; kk++) {
            float af[8], bf[8];
            *(float4*)&af[0] = *(const float4*)&As[kk][ty * 8];
            *(float4*)&af[4] = *(const float4*)&As[kk][ty * 8 + 4];
            *(float4*)&bf[0] = *(const float4*)&Bs[kk][tx * 8];
            *(float4*)&bf[4] = *(const float4*)&Bs[kk][tx * 8 + 4];
#pragma unroll
            for (int i = 0; i < 8; i++)
#pragma unroll
                for (int j = 0; j < 8; j++)
                    acc[i][j] = fmaf(af[i], bf[j], acc[i][j]);
        }
    }

    // projection: hid = relu(acc + b); p[i][c] = sum_j hid[i][j] * Wm2[tx*8+j][c]
    float p0[8], p1[8];
#pragma unroll
    for (int i = 0; i < 8; i++) { p0[i] = 0.f; p1[i] = 0.f; }
#pragma unroll
    for (int j = 0; j < 8; j++) {
        float w0 = wm2s[(tx * 8 + j) * 2];
        float w1 = wm2s[(tx * 8 + j) * 2 + 1];
        float b = bsm[tx * 8 + j];
#pragma unroll
        for (int i = 0; i < 8; i++) {
            float hv = fmaxf(acc[i][j] + b, 0.f);
            p0[i] = fmaf(hv, w0, p0[i]);
            p1[i] = fmaf(hv, w1, p1[i]);
        }
    }
    // reduce across the 8 lanes sharing ty (tx = bits 0-2 of tid, same warp)
    const unsigned FULL = 0xffffffffu;
#pragma unroll
    for (int off = 4; off > 0; off >>= 1) {
#pragma unroll
        for (int i = 0; i < 8; i++) {
            p0[i] += __shfl_xor_sync(FULL, p0[i], off);
            p1[i] += __shfl_xor_sync(FULL, p1[i], off);
        }
    }
    if (tx == 0) {
#pragma unroll
        for (int i = 0; i < 8; i++) {
            int row = m0 + ty * 8 + i;
            if (row < M) {
                out[(size_t)row * 2]     = p0[i] + bm2s[0];
                out[(size_t)row * 2 + 1] = p1[i] + bm2s[1];
            }
        }
    }
}

// ---------------- conv aggregate (CSR-by-dst gather, unroll-4 MLP) ----------------
__global__ __launch_bounds__(256)
void k_conv(const float* __restrict__ h, const float* __restrict__ dinv,
            const float* __restrict__ bias, const float* __restrict__ res,
            const int* __restrict__ offD, const int* __restrict__ srcD,
            float* __restrict__ out, int N) {
    int warp = (blockIdx.x * blockDim.x + threadIdx.x) >> 5;
    int lane = threadIdx.x & 31;
    if (warp >= N) return;
    int n = warp;
    int beg = offD[n], end = offD[n + 1];
    int cnt = end - beg;
    const unsigned FULL = 0xffffffffu;

    float2 a0 = *(const float2*)(h + (size_t)n * 64 + 2 * lane);  // self loop
    float2 a1 = make_float2(0.f, 0.f);
    for (int base = 0; base < cnt; base += 32) {
        int idx = beg + base + lane;
        int sv = srcD[idx < end ? idx : (end - 1)];
        int m = min(32, cnt - base);
        int j = 0;
        for (; j + 4 <= m; j += 4) {
            int s0 = __shfl_sync(FULL, sv, j);
            int s1 = __shfl_sync(FULL, sv, j + 1);
            int s2 = __shfl_sync(FULL, sv, j + 2);
            int s3 = __shfl_sync(FULL, sv, j + 3);
            float2 v0 = *(const float2*)(h + (size_t)s0 * 64 + 2 * lane);
            float2 v1 = *(const float2*)(h + (size_t)s1 * 64 + 2 * lane);
            float2 v2 = *(const float2*)(h + (size_t)s2 * 64 + 2 * lane);
            float2 v3 = *(const float2*)(h + (size_t)s3 * 64 + 2 * lane);
            a0.x += v0.x; a0.y += v0.y;
            a1.x += v1.x; a1.y += v1.y;
            a0.x += v2.x; a0.y += v2.y;
            a1.x += v3.x; a1.y += v3.y;
        }
        for (; j < m; j++) {
            int s = __shfl_sync(FULL, sv, j);
            float2 v = *(const float2*)(h + (size_t)s * 64 + 2 * lane);
            a0.x += v.x; a0.y += v.y;
        }
    }
    float2 a = make_float2(a0.x + a1.x, a0.y + a1.y);
    float di = dinv[n];
    float2 b = *(const float2*)(bias + 2 * lane);
    float2 o;
    o.x = a.x * di + b.x;
    o.y = a.y * di + b.y;
    if (res) {
        float2 r = *(const float2*)(res + (size_t)n * 64 + 2 * lane);
        o.x += r.x;
        o.y += r.y;
    }
    o.x = fmaxf(o.x, 0.0f);
    o.y = fmaxf(o.y, 0.0f);
    *(float2*)(out + (size_t)n * 64 + 2 * lane) = o;
}

// ---------------- fusion aggregate (CSR-by-src, pipelined gather, We in smem) ----
__global__ __launch_bounds__(256)
void k_fusion(const float* __restrict__ x2, const float* __restrict__ xenc,
              const float* __restrict__ tw, const float* __restrict__ eattr,
              const float* __restrict__ We, const float* __restrict__ be,
              const int* __restrict__ offS, const int4* __restrict__ epk,
              float* __restrict__ nf, int N) {
    __shared__ float Ws[32 * 64];
    __shared__ float bes[64];
    {
        int tid = threadIdx.x;
        for (int i = tid; i < 32 * 64; i += 256) Ws[i] = We[i];
        if (tid < 64) bes[tid] = be[tid];
    }
    __syncthreads();

    int lane = threadIdx.x & 31;
    int warp = (blockIdx.x * blockDim.x + threadIdx.x) >> 5;
    if (warp >= N) return;
    int n = warp;
    int beg = offS[n], end = offS[n + 1];
    int cnt = end - beg;
    const unsigned FULL = 0xffffffffu;

    float2 bee = *(const float2*)&bes[2 * lane];
    float* o = nf + (size_t)n * 256;
    float2 f0 = *(const float2*)(x2 + (size_t)n * 64 + 2 * lane);

    if (cnt == 0) {
        float2 xe = *(const float2*)(xenc + (size_t)n * 64 + 2 * lane);
        *(float2*)(o + 2 * lane) = xe;
        *(float2*)(o + 64 + 2 * lane) = xe;
        *(float2*)(o + 128 + 2 * lane) = xe;
        *(float2*)(o + 192 + 2 * lane) = xe;
        return;
    }

    // chunk of edge records in lane regs; 2-deep pipeline over edges
    int idx0 = beg + lane;
    int4 my = epk[idx0 < end ? idx0 : (end - 1)];
    int e = __shfl_sync(FULL, my.x, 0);
    int d = __shfl_sync(FULL, my.y, 0);
    int t = __shfl_sync(FULL, my.z, 0);
    float  ean = eattr[(size_t)e * 32 + lane];
    float2 xdn = *(const float2*)(x2 + (size_t)d * 64 + 2 * lane);
    float2 ten = *(const float2*)(tw + (size_t)t * 64 + 2 * lane);

    float2 a0 = make_float2(0.f, 0.f), a1 = a0, a2 = a0;
    for (int j = 0; j < cnt; j++) {
        float ea = ean;
        float2 xd = xdn, te = ten;
        int jn = j + 1;
        if (jn < cnt) {
            int jj = jn & 31;
            if (jj == 0) {
                int idx = beg + jn + lane;
                my = epk[idx < end ? idx : (end - 1)];
            }
            e = __shfl_sync(FULL, my.x, jj);
            d = __shfl_sync(FULL, my.y, jj);
            t = __shfl_sync(FULL, my.z, jj);
            ean = eattr[(size_t)e * 32 + lane];
            xdn = *(const float2*)(x2 + (size_t)d * 64 + 2 * lane);
            ten = *(const float2*)(tw + (size_t)t * 64 + 2 * lane);
        }
        a0.x += xd.x; a0.y += xd.y;
        a2.x += te.x; a2.y += te.y;
        float m0 = bee.x, m1 = bee.y;
#pragma unroll
        for (int k = 0; k < 32; k++) {
            float v = __shfl_sync(FULL, ea, k);
            float2 wk = *(const float2*)&Ws[k * 64 + 2 * lane];
            m0 = fmaf(v, wk.x, m0);
            m1 = fmaf(v, wk.y, m1);
        }
        a1.x += fmaxf(m0, 0.0f);
        a1.y += fmaxf(m1, 0.0f);
    }
    float inv = 1.0f / (float)cnt;
    float2 f1 = make_float2(a0.x * inv, a0.y * inv);
    float2 f2 = make_float2(a1.x * inv, a1.y * inv);
    float2 f3 = make_float2(a2.x * inv, a2.y * inv);

    float s = fabsf(f0.x) + fabsf(f0.y) + fabsf(f1.x) + fabsf(f1.y) +
              fabsf(f2.x) + fabsf(f2.y) + fabsf(f3.x) + fabsf(f3.y);
#pragma unroll
    for (int off = 16; off > 0; off >>= 1) s += __shfl_xor_sync(FULL, s, off);

    if (s < 1e-6f) {
        float2 xe = *(const float2*)(xenc + (size_t)n * 64 + 2 * lane);
        *(float2*)(o + 2 * lane) = xe;
        *(float2*)(o + 64 + 2 * lane) = xe;
        *(float2*)(o + 128 + 2 * lane) = xe;
        *(float2*)(o + 192 + 2 * lane) = xe;
    } else {
        *(float2*)(o + 2 * lane) = f0;
        *(float2*)(o + 64 + 2 * lane) = f1;
        *(float2*)(o + 128 + 2 * lane) = f2;
        *(float2*)(o + 192 + 2 * lane) = f3;
    }
}

// ---------------- host launcher ----------------
extern "C" void kernel_launch(void* const* d_in, const int* in_sizes, int n_in,
                              void* d_out, int out_size) {
    const float* x    = (const float*)d_in[0];
    const int*   ei   = (const int*)d_in[1];
    const float* eatt = (const float*)d_in[2];
    const int*   ts   = (const int*)d_in[3];
    const float* Wn   = (const float*)d_in[4];
    const float* bn   = (const float*)d_in[5];
    const float* We   = (const float*)d_in[6];
    const float* be   = (const float*)d_in[7];
    const float* Temb = (const float*)d_in[8];
    const float* Wt   = (const float*)d_in[9];
    const float* bt   = (const float*)d_in[10];
    const float* Wc1  = (const float*)d_in[11];
    const float* bc1  = (const float*)d_in[12];
    const float* Wc2  = (const float*)d_in[13];
    const float* bc2  = (const float*)d_in[14];
    const float* Wr   = (const float*)d_in[15];
    const float* br   = (const float*)d_in[16];
    const float* Wm1  = (const float*)d_in[17];
    const float* bm1  = (const float*)d_in[18];
    const float* Wm2  = (const float*)d_in[19];
    const float* bm2  = (const float*)d_in[20];

    const int N = in_sizes[0] / 128;
    const int E = in_sizes[3];
    const int* src = ei;
    const int* dst = ei + E;

    float *p_xenc, *p_h, *p_x1, *p_x2, *p_res, *p_tw, *p_dinv, *p_nf;
    int *p_deg, *p_offD, *p_offS, *p_curD, *p_curS, *p_bsum, *p_srcD;
    int4* p_epk;
    cudaGetSymbolAddress((void**)&p_xenc, g_xenc);
    cudaGetSymbolAddress((void**)&p_h, g_h);
    cudaGetSymbolAddress((void**)&p_x1, g_x1);
    cudaGetSymbolAddress((void**)&p_x2, g_x2);
    cudaGetSymbolAddress((void**)&p_res, g_res);
    cudaGetSymbolAddress((void**)&p_tw, g_tw);
    cudaGetSymbolAddress((void**)&p_dinv, g_dinv);
    cudaGetSymbolAddress((void**)&p_nf, g_nf);
    cudaGetSymbolAddress((void**)&p_deg, g_deg);
    cudaGetSymbolAddress((void**)&p_offD, g_offD);
    cudaGetSymbolAddress((void**)&p_offS, g_offS);
    cudaGetSymbolAddress((void**)&p_curD, g_curD);
    cudaGetSymbolAddress((void**)&p_curS, g_curS);
    cudaGetSymbolAddress((void**)&p_bsum, g_bsum);
    cudaGetSymbolAddress((void**)&p_srcD, g_srcD);
    cudaGetSymbolAddress((void**)&p_epk, g_epk);

    int* p_indeg = p_deg;
    int* p_outdeg = p_deg + N;

    float* outp = (float*)d_out;

    const int NB = (N + 1023) / 1024;  // <=98

    cudaMemsetAsync(p_deg, 0, (size_t)2 * N * sizeof(int));

    k_hist<<<(E + 255) / 256, 256>>>(src, dst, p_indeg, p_outdeg, E);
    k_scan_blk<<<dim3(NB, 2), 1024>>>(p_indeg, p_outdeg, p_offD, p_offS, p_dinv, p_bsum, N);
    k_scan_top<<<dim3(1, 2), 128>>>(p_bsum, NB);
    k_scan_add<<<dim3(NB, 2), 1024>>>(p_offD, p_offS, p_curD, p_curS, p_bsum, N);
    k_scatter_ids<<<(E + 255) / 256, 256>>>(src, dst, ts, p_curD, p_curS, p_srcD, p_epk, E);

    k_ttable<<<1000, 64>>>(Temb, Wt, bt, p_tw);

    const int g256 = (N + 255) / 256;
    const int g128 = (N + 127) / 128;
    const int wg = (N * 32 + 255) / 256;

    // x_enc = relu(x @ Wn + bn)
    k_gemm<128, true><<<g256, 256>>>(x, Wn, bn, nullptr, p_xenc, N);

    // conv1 h' + residual in one pass over x_enc
    k_gemm_dual<<<g128, 256>>>(p_xenc, Wc1, Wr, br, p_dinv, p_h, p_res, N);
    k_conv<<<wg, 256>>>(p_h, p_dinv, bc1, nullptr, p_offD, p_srcD, p_x1, N);

    // conv2 (+res)
    k_gemm<64, false><<<g256, 256>>>(p_x1, Wc2, nullptr, p_dinv, p_h, N);
    k_conv<<<wg, 256>>>(p_h, p_dinv, bc2, p_res, p_offD, p_srcD, p_x2, N);

    // fusion gather (edge matvec inline, We in smem, pipelined loads)
    k_fusion<<<wg, 256>>>(p_x2, p_xenc, p_tw, eatt, We, be, p_offS, p_epk, p_nf, N);

    // classifier fused with final 64->2 projection (in-register + shfl reduce)
    k_gemm_cls<<<g256, 256>>>(p_nf, Wm1, bm1, Wm2, bm2, outp, N);
}

// round 11
// speedup vs baseline: 1.0877x; 1.0877x over previous
#include <cuda_runtime.h>
#include <cstdint>

#define MAXN 100000
#define MAXE 800000
#define H 64
#define SCAN_PAD (MAXN + 2048)

// ---------------- device scratch ----------------
__device__ float g_xenc[MAXN * H];
__device__ float g_h[MAXN * H];
__device__ float g_x1[MAXN * H];
__device__ float g_x2[MAXN * H];
__device__ float g_res[MAXN * H];
__device__ float g_tw[1000 * H];
__device__ float g_dinv[MAXN];
__device__ float g_nf[MAXN * 4 * H];

__device__ int  g_deg[2 * MAXN];
__device__ int  g_offD[SCAN_PAD];
__device__ int  g_offS[SCAN_PAD];
__device__ int  g_curD[MAXN];
__device__ int  g_curS[MAXN];
__device__ int  g_bsum[256];
__device__ int  g_srcD[MAXE];
__device__ int4 g_epk[MAXE];   // {e, dst, ts, 0} permuted by src

// ---------------- histogram ----------------
__global__ void k_hist(const int* __restrict__ src, const int* __restrict__ dst,
                       int* __restrict__ indeg, int* __restrict__ outdeg, int E) {
    int i = blockIdx.x * blockDim.x + threadIdx.x;
    if (i < E) {
        atomicAdd(&indeg[dst[i]], 1);
        atomicAdd(&outdeg[src[i]], 1);
    }
}

// ---------------- exclusive scan, two arrays at once (gridDim.y=2) ----------------
__global__ void k_scan_blk(const int* __restrict__ indeg, const int* __restrict__ outdeg,
                           int* __restrict__ offD, int* __restrict__ offS,
                           float* __restrict__ dinv, int* __restrict__ bsum, int n) {
    __shared__ int sm[1024];
    int y = blockIdx.y;
    const int* in = y ? outdeg : indeg;
    int* out = y ? offS : offD;
    int tid = threadIdx.x;
    int i = blockIdx.x * 1024 + tid;
    int v = (i < n) ? in[i] : 0;
    if (y == 0 && i < n) dinv[i] = rsqrtf((float)v + 1.0f);
    sm[tid] = v;
    __syncthreads();
#pragma unroll
    for (int off = 1; off < 1024; off <<= 1) {
        int t = (tid >= off) ? sm[tid - off] : 0;
        __syncthreads();
        sm[tid] += t;
        __syncthreads();
    }
    out[i] = sm[tid] - v;  // exclusive
    if (tid == 1023) bsum[y * 128 + blockIdx.x] = sm[1023];
}

__global__ void k_scan_top(int* __restrict__ bsum, int nb) {
    __shared__ int sm[128];
    int y = blockIdx.y;
    int tid = threadIdx.x;
    int v = (tid < nb) ? bsum[y * 128 + tid] : 0;
    sm[tid] = v;
    __syncthreads();
#pragma unroll
    for (int off = 1; off < 128; off <<= 1) {
        int t = (tid >= off) ? sm[tid - off] : 0;
        __syncthreads();
        sm[tid] += t;
        __syncthreads();
    }
    if (tid < nb) bsum[y * 128 + tid] = sm[tid] - v;
}

__global__ void k_scan_add(int* __restrict__ offD, int* __restrict__ offS,
                           int* __restrict__ curD, int* __restrict__ curS,
                           const int* __restrict__ bsum, int n) {
    int y = blockIdx.y;
    int* out = y ? offS : offD;
    int* cur = y ? curS : curD;
    int i = blockIdx.x * 1024 + threadIdx.x;
    int v = out[i] + bsum[y * 128 + blockIdx.x];
    out[i] = v;
    if (i < n) cur[i] = v;
}

// ---------------- permute edges into CSR order ----------------
__global__ void k_scatter_ids(const int* __restrict__ src, const int* __restrict__ dst,
                              const int* __restrict__ ts,
                              int* __restrict__ curD, int* __restrict__ curS,
                              int* __restrict__ srcD, int4* __restrict__ epk, int E) {
    int e = blockIdx.x * blockDim.x + threadIdx.x;
    if (e >= E) return;
    int s = src[e], d = dst[e];
    int p = atomicAdd(&curD[d], 1);
    srcD[p] = s;
    int q = atomicAdd(&curS[s], 1);
    epk[q] = make_int4(e, d, min(max(ts[e], 0), 999), 0);
}

// ---------------- time table ----------------
__global__ void k_ttable(const float* __restrict__ Temb, const float* __restrict__ Wt,
                         const float* __restrict__ bt, float* __restrict__ tw) {
    __shared__ float er[H];
    int t = blockIdx.x;
    int c = threadIdx.x;
    er[c] = Temb[t * H + c];
    __syncthreads();
    float a = bt[c];
#pragma unroll
    for (int k = 0; k < H; k++) a += er[k] * Wt[k * H + c];
    tw[t * H + c] = fmaxf(a, 0.0f);
}

// ---------------- tiled SGEMM: [M,K] @ [K,64], BM=128, 8x4, double-buffered ----------
template <int K, bool RELU>
__global__ __launch_bounds__(256)
void k_gemm(const float* __restrict__ A, const float* __restrict__ W,
            const float* __restrict__ bias, const float* __restrict__ rowscale,
            float* __restrict__ C, int M) {
    __shared__ float As[2][16][132];
    __shared__ float Bs[2][16][64];
    __shared__ float bsm[64];

    const int tid = threadIdx.x;
    const int tx = tid & 15;
    const int ty = tid >> 4;
    const int m0 = blockIdx.x * 128;

    if (tid < 64) bsm[tid] = bias ? bias[tid] : 0.0f;

    // per-thread load slots: A tile is 512 float4 (2 per thread), B tile is 256 float4 (1 per thread)
    const int rowA0 = tid >> 2;            // f = tid
    const int rowA1 = (tid + 256) >> 2;    // f = tid + 256
    const int kqA = tid & 3;
    const int krowB = tid >> 4, cqB = tid & 15;

    float acc[8][4];
#pragma unroll
    for (int i = 0; i < 8; i++)
#pragma unroll
        for (int j = 0; j < 4; j++) acc[i][j] = 0.0f;

    float4 sa0, sa1, sb;
    // prologue: load tile 0
    {
        int gr0 = m0 + rowA0;
        sa0 = make_float4(0.f, 0.f, 0.f, 0.f);
        if (gr0 < M) sa0 = *(const float4*)(A + (size_t)gr0 * K + kqA * 4);
        int gr1 = m0 + rowA1;
        sa1 = make_float4(0.f, 0.f, 0.f, 0.f);
        if (gr1 < M) sa1 = *(const float4*)(A + (size_t)gr1 * K + kqA * 4);
        sb = *(const float4*)(W + (size_t)krowB * 64 + cqB * 4);
        As[0][kqA * 4 + 0][rowA0] = sa0.x;
        As[0][kqA * 4 + 1][rowA0] = sa0.y;
        As[0][kqA * 4 + 2][rowA0] = sa0.z;
        As[0][kqA * 4 + 3][rowA0] = sa0.w;
        As[0][kqA * 4 + 0][rowA1] = sa1.x;
        As[0][kqA * 4 + 1][rowA1] = sa1.y;
        As[0][kqA * 4 + 2][rowA1] = sa1.z;
        As[0][kqA * 4 + 3][rowA1] = sa1.w;
        *(float4*)&Bs[0][krowB][cqB * 4] = sb;
    }
    __syncthreads();

    int buf = 0;
    for (int kc = 0; kc < K; kc += 16) {
        const int kn = kc + 16;
        const bool more = (kn < K);
        // issue next tile's global loads (land during compute)
        if (more) {
            int gr0 = m0 + rowA0;
            sa0 = make_float4(0.f, 0.f, 0.f, 0.f);
            if (gr0 < M) sa0 = *(const float4*)(A + (size_t)gr0 * K + kn + kqA * 4);
            int gr1 = m0 + rowA1;
            sa1 = make_float4(0.f, 0.f, 0.f, 0.f);
            if (gr1 < M) sa1 = *(const float4*)(A + (size_t)gr1 * K + kn + kqA * 4);
            sb = *(const float4*)(W + (size_t)(kn + krowB) * 64 + cqB * 4);
        }
        // compute on current buffer
#pragma unroll
        for (int kk = 0; kk < 16; kk++) {
            float af[8], bf[4];
            *(float4*)&af[0] = *(const float4*)&As[buf][kk][ty * 8];
            *(float4*)&af[4] = *(const float4*)&As[buf][kk][ty * 8 + 4];
            *(float4*)&bf[0] = *(const float4*)&Bs[buf][kk][tx * 4];
#pragma unroll
            for (int i = 0; i < 8; i++)
#pragma unroll
                for (int j = 0; j < 4; j++)
                    acc[i][j] = fmaf(af[i], bf[j], acc[i][j]);
        }
        // stage next tile into the alternate buffer, single sync per iteration
        if (more) {
            int nb = buf ^ 1;
            As[nb][kqA * 4 + 0][rowA0] = sa0.x;
            As[nb][kqA * 4 + 1][rowA0] = sa0.y;
            As[nb][kqA * 4 + 2][rowA0] = sa0.z;
            As[nb][kqA * 4 + 3][rowA0] = sa0.w;
            As[nb][kqA * 4 + 0][rowA1] = sa1.x;
            As[nb][kqA * 4 + 1][rowA1] = sa1.y;
            As[nb][kqA * 4 + 2][rowA1] = sa1.z;
            As[nb][kqA * 4 + 3][rowA1] = sa1.w;
            *(float4*)&Bs[nb][krowB][cqB * 4] = sb;
            __syncthreads();
            buf = nb;
        }
    }

#pragma unroll
    for (int i = 0; i < 8; i++) {
        int row = m0 + ty * 8 + i;
        if (row < M) {
            float sc = rowscale ? rowscale[row] : 1.0f;
            float4 v;
            v.x = acc[i][0] + bsm[tx * 4 + 0];
            v.y = acc[i][1] + bsm[tx * 4 + 1];
            v.z = acc[i][2] + bsm[tx * 4 + 2];
            v.w = acc[i][3] + bsm[tx * 4 + 3];
            if (RELU) {
                v.x = fmaxf(v.x, 0.f); v.y = fmaxf(v.y, 0.f);
                v.z = fmaxf(v.z, 0.f); v.w = fmaxf(v.w, 0.f);
            }
            v.x *= sc; v.y *= sc; v.z *= sc; v.w *= sc;
            *(float4*)(C + (size_t)row * 64 + tx * 4) = v;
        }
    }
}

// ---------------- dual SGEMM: H = (A@W1)*dinv[row], R = A@W2 + b2  (K=64) --------
__global__ __launch_bounds__(256)
void k_gemm_dual(const float* __restrict__ A, const float* __restrict__ W1,
                 const float* __restrict__ W2, const float* __restrict__ b2,
                 const float* __restrict__ dinv, float* __restrict__ Hh,
                 float* __restrict__ R, int M) {
    __shared__ float As[16][132];
    __shared__ float Bs[16][128];
    __shared__ float bsm[64];

    const int tid = threadIdx.x;
    const int tx = tid & 15;
    const int ty = tid >> 4;
    const int m0 = blockIdx.x * 128;

    if (tid < 64) bsm[tid] = b2[tid];

    float acc[8][8];
#pragma unroll
    for (int i = 0; i < 8; i++)
#pragma unroll
        for (int j = 0; j < 8; j++) acc[i][j] = 0.0f;

    for (int kc = 0; kc < 64; kc += 16) {
        __syncthreads();
#pragma unroll
        for (int f = tid; f < 512; f += 256) {
            int row = f >> 2, kq = f & 3;
            int gr = m0 + row;
            float4 v = make_float4(0.f, 0.f, 0.f, 0.f);
            if (gr < M) v = *(const float4*)(A + (size_t)gr * 64 + kc + kq * 4);
            As[kq * 4 + 0][row] = v.x;
            As[kq * 4 + 1][row] = v.y;
            As[kq * 4 + 2][row] = v.z;
            As[kq * 4 + 3][row] = v.w;
        }
#pragma unroll
        for (int f = tid; f < 512; f += 256) {
            int krow = f >> 5, cq = f & 31;
            float4 v = (cq < 16)
                ? *(const float4*)(W1 + (size_t)(kc + krow) * 64 + cq * 4)
                : *(const float4*)(W2 + (size_t)(kc + krow) * 64 + (cq - 16) * 4);
            *(float4*)&Bs[krow][cq * 4] = v;
        }
        __syncthreads();
#pragma unroll
        for (int kk = 0; kk < 16; kk++) {
            float af[8], bf[8];
            *(float4*)&af[0] = *(const float4*)&As[kk][ty * 8];
            *(float4*)&af[4] = *(const float4*)&As[kk][ty * 8 + 4];
            *(float4*)&bf[0] = *(const float4*)&Bs[kk][tx * 8];
            *(float4*)&bf[4] = *(const float4*)&Bs[kk][tx * 8 + 4];
#pragma unroll
            for (int i = 0; i < 8; i++)
#pragma unroll
                for (int j = 0; j < 8; j++)
                    acc[i][j] = fmaf(af[i], bf[j], acc[i][j]);
        }
    }

    const bool second = (tx >= 8);
    const int c0 = second ? (tx - 8) * 8 : tx * 8;
#pragma unroll
    for (int i = 0; i < 8; i++) {
        int row = m0 + ty * 8 + i;
        if (row < M) {
            if (!second) {
                float sc = dinv[row];
                float4 v0, v1;
                v0.x = acc[i][0] * sc; v0.y = acc[i][1] * sc;
                v0.z = acc[i][2] * sc; v0.w = acc[i][3] * sc;
                v1.x = acc[i][4] * sc; v1.y = acc[i][5] * sc;
                v1.z = acc[i][6] * sc; v1.w = acc[i][7] * sc;
                *(float4*)(Hh + (size_t)row * 64 + c0) = v0;
                *(float4*)(Hh + (size_t)row * 64 + c0 + 4) = v1;
            } else {
                float4 v0, v1;
                v0.x = acc[i][0] + bsm[c0 + 0]; v0.y = acc[i][1] + bsm[c0 + 1];
                v0.z = acc[i][2] + bsm[c0 + 2]; v0.w = acc[i][3] + bsm[c0 + 3];
                v1.x = acc[i][4] + bsm[c0 + 4]; v1.y = acc[i][5] + bsm[c0 + 5];
                v1.z = acc[i][6] + bsm[c0 + 6]; v1.w = acc[i][7] + bsm[c0 + 7];
                *(float4*)(R + (size_t)row * 64 + c0) = v0;
                *(float4*)(R + (size_t)row * 64 + c0 + 4) = v1;
            }
        }
    }
}

// ---------------- classifier: hid=relu(A@Wm1+bm1) in smem, out=hid@Wm2+bm2 ------
__global__ __launch_bounds__(256)
void k_gemm_cls(const float* __restrict__ A, const float* __restrict__ W,
                const float* __restrict__ bias, const float* __restrict__ Wm2,
                const float* __restrict__ bm2, float* __restrict__ out, int M) {
    __shared__ __align__(16) float pool[128 * 68];      // 34816 B (tile phase)
    float (*As)[132] = (float(*)[132])pool;             // 2112 floats
    float (*Bs)[64]  = (float(*)[64])(pool + 2112);     // 1024 floats
    __shared__ float bsm[64];
    __shared__ float wm2s[128];
    __shared__ float bm2s[2];

    const int tid = threadIdx.x;
    const int tx = tid & 15;
    const int ty = tid >> 4;
    const int m0 = blockIdx.x * 128;

    if (tid < 64) bsm[tid] = bias[tid];
    if (tid < 128) wm2s[tid] = Wm2[tid];
    if (tid < 2) bm2s[tid] = bm2[tid];

    float acc[8][4];
#pragma unroll
    for (int i = 0; i < 8; i++)
#pragma unroll
        for (int j = 0; j < 4; j++) acc[i][j] = 0.0f;

    for (int kc = 0; kc < 256; kc += 16) {
        __syncthreads();
#pragma unroll
        for (int f = tid; f < 512; f += 256) {
            int row = f >> 2, kq = f & 3;
            int gr = m0 + row;
            float4 v = make_float4(0.f, 0.f, 0.f, 0.f);
            if (gr < M) v = *(const float4*)(A + (size_t)gr * 256 + kc + kq * 4);
            As[kq * 4 + 0][row] = v.x;
            As[kq * 4 + 1][row] = v.y;
            As[kq * 4 + 2][row] = v.z;
            As[kq * 4 + 3][row] = v.w;
        }
        {
            int krow = tid >> 4, cq = tid & 15;
            *(float4*)&Bs[krow][cq * 4] = *(const float4*)(W + (size_t)(kc + krow) * 64 + cq * 4);
        }
        __syncthreads();
#pragma unroll
        for (int kk = 0; kk < 16; kk++) {
            float af[8], bf[4];
            *(float4*)&af[0] = *(const float4*)&As[kk][ty * 8];
            *(float4*)&af[4] = *(const float4*)&As[kk][ty * 8 + 4];
            *(float4*)&bf[0] = *(const float4*)&Bs[kk][tx * 4];
#pragma unroll
            for (int i = 0; i < 8; i++)
#pragma unroll
                for (int j = 0; j < 4; j++)
                    acc[i][j] = fmaf(af[i], bf[j], acc[i][j]);
        }
    }

    // write relu(hid) tile into smem (overwrites As/Bs)
    __syncthreads();
#pragma unroll
    for (int i = 0; i < 8; i++) {
        int lr = ty * 8 + i;
        float4 v;
        v.x = fmaxf(acc[i][0] + bsm[tx * 4 + 0], 0.f);
        v.y = fmaxf(acc[i][1] + bsm[tx * 4 + 1], 0.f);
        v.z = fmaxf(acc[i][2] + bsm[tx * 4 + 2], 0.f);
        v.w = fmaxf(acc[i][3] + bsm[tx * 4 + 3], 0.f);
        *(float4*)&pool[lr * 68 + tx * 4] = v;
    }
    __syncthreads();

    // out[row] = hid_row @ Wm2 + bm2 : thread t -> row t>>1, col t&1
    int r = tid >> 1, c = tid & 1;
    int row = m0 + r;
    if (row < M) {
        const float* hr = &pool[r * 68];
        float s = 0.0f;
#pragma unroll
        for (int k = 0; k < 64; k++) s = fmaf(hr[k], wm2s[k * 2 + c], s);
        out[(size_t)row * 2 + c] = s + bm2s[c];
    }
}

// ---------------- conv aggregate (CSR-by-dst gather, fused finalize) ----------------
__global__ __launch_bounds__(256)
void k_conv(const float* __restrict__ h, const float* __restrict__ dinv,
            const float* __restrict__ bias, const float* __restrict__ res,
            const int* __restrict__ offD, const int* __restrict__ srcD,
            float* __restrict__ out, int N) {
    int warp = (blockIdx.x * blockDim.x + threadIdx.x) >> 5;
    int lane = threadIdx.x & 31;
    if (warp >= N) return;
    int n = warp;
    int beg = offD[n], end = offD[n + 1];
    int cnt = end - beg;
    const unsigned FULL = 0xffffffffu;

    float2 a = *(const float2*)(h + (size_t)n * 64 + 2 * lane);  // self loop
    for (int base = 0; base < cnt; base += 32) {
        int idx = beg + base + lane;
        int sv = srcD[idx < end ? idx : (end - 1)];
        int m = min(32, cnt - base);
        for (int j = 0; j < m; j++) {
            int s = __shfl_sync(FULL, sv, j);
            float2 v = *(const float2*)(h + (size_t)s * 64 + 2 * lane);
            a.x += v.x;
            a.y += v.y;
        }
    }
    float di = dinv[n];
    float2 b = *(const float2*)(bias + 2 * lane);
    float2 o;
    o.x = a.x * di + b.x;
    o.y = a.y * di + b.y;
    if (res) {
        float2 r = *(const float2*)(res + (size_t)n * 64 + 2 * lane);
        o.x += r.x;
        o.y += r.y;
    }
    o.x = fmaxf(o.x, 0.0f);
    o.y = fmaxf(o.y, 0.0f);
    *(float2*)(out + (size_t)n * 64 + 2 * lane) = o;
}

// ---------------- fusion aggregate (CSR-by-src, pipelined gather, We in smem) ----
__global__ __launch_bounds__(256)
void k_fusion(const float* __restrict__ x2, const float* __restrict__ xenc,
              const float* __restrict__ tw, const float* __restrict__ eattr,
              const float* __restrict__ We, const float* __restrict__ be,
              const int* __restrict__ offS, const int4* __restrict__ epk,
              float* __restrict__ nf, int N) {
    __shared__ float Ws[32 * 64];
    __shared__ float bes[64];
    {
        int tid = threadIdx.x;
        for (int i = tid; i < 32 * 64; i += 256) Ws[i] = We[i];
        if (tid < 64) bes[tid] = be[tid];
    }
    __syncthreads();

    int lane = threadIdx.x & 31;
    int warp = (blockIdx.x * blockDim.x + threadIdx.x) >> 5;
    if (warp >= N) return;
    int n = warp;
    int beg = offS[n], end = offS[n + 1];
    int cnt = end - beg;
    const unsigned FULL = 0xffffffffu;

    float2 bee = *(const float2*)&bes[2 * lane];
    float* o = nf + (size_t)n * 256;
    float2 f0 = *(const float2*)(x2 + (size_t)n * 64 + 2 * lane);

    if (cnt == 0) {
        float2 xe = *(const float2*)(xenc + (size_t)n * 64 + 2 * lane);
        *(float2*)(o + 2 * lane) = xe;
        *(float2*)(o + 64 + 2 * lane) = xe;
        *(float2*)(o + 128 + 2 * lane) = xe;
        *(float2*)(o + 192 + 2 * lane) = xe;
        return;
    }

    // chunk of edge records in lane regs; 2-deep pipeline over edges
    int idx0 = beg + lane;
    int4 my = epk[idx0 < end ? idx0 : (end - 1)];
    int e = __shfl_sync(FULL, my.x, 0);
    int d = __shfl_sync(FULL, my.y, 0);
    int t = __shfl_sync(FULL, my.z, 0);
    float  ean = eattr[(size_t)e * 32 + lane];
    float2 xdn = *(const float2*)(x2 + (size_t)d * 64 + 2 * lane);
    float2 ten = *(const float2*)(tw + (size_t)t * 64 + 2 * lane);

    float2 a0 = make_float2(0.f, 0.f), a1 = a0, a2 = a0;
    for (int j = 0; j < cnt; j++) {
        float ea = ean;
        float2 xd = xdn, te = ten;
        int jn = j + 1;
        if (jn < cnt) {
            int jj = jn & 31;
            if (jj == 0) {
                int idx = beg + jn + lane;
                my = epk[idx < end ? idx : (end - 1)];
            }
            e = __shfl_sync(FULL, my.x, jj);
            d = __shfl_sync(FULL, my.y, jj);
            t = __shfl_sync(FULL, my.z, jj);
            ean = eattr[(size_t)e * 32 + lane];
            xdn = *(const float2*)(x2 + (size_t)d * 64 + 2 * lane);
            ten = *(const float2*)(tw + (size_t)t * 64 + 2 * lane);
        }
        a0.x += xd.x; a0.y += xd.y;
        a2.x += te.x; a2.y += te.y;
        float m0 = bee.x, m1 = bee.y;
#pragma unroll
        for (int k = 0; k < 32; k++) {
            float v = __shfl_sync(FULL, ea, k);
            float2 wk = *(const float2*)&Ws[k * 64 + 2 * lane];
            m0 = fmaf(v, wk.x, m0);
            m1 = fmaf(v, wk.y, m1);
        }
        a1.x += fmaxf(m0, 0.0f);
        a1.y += fmaxf(m1, 0.0f);
    }
    float inv = 1.0f / (float)cnt;
    float2 f1 = make_float2(a0.x * inv, a0.y * inv);
    float2 f2 = make_float2(a1.x * inv, a1.y * inv);
    float2 f3 = make_float2(a2.x * inv, a2.y * inv);

    float s = fabsf(f0.x) + fabsf(f0.y) + fabsf(f1.x) + fabsf(f1.y) +
              fabsf(f2.x) + fabsf(f2.y) + fabsf(f3.x) + fabsf(f3.y);
#pragma unroll
    for (int off = 16; off > 0; off >>= 1) s += __shfl_xor_sync(FULL, s, off);

    if (s < 1e-6f) {
        float2 xe = *(const float2*)(xenc + (size_t)n * 64 + 2 * lane);
        *(float2*)(o + 2 * lane) = xe;
        *(float2*)(o + 64 + 2 * lane) = xe;
        *(float2*)(o + 128 + 2 * lane) = xe;
        *(float2*)(o + 192 + 2 * lane) = xe;
    } else {
        *(float2*)(o + 2 * lane) = f0;
        *(float2*)(o + 64 + 2 * lane) = f1;
        *(float2*)(o + 128 + 2 * lane) = f2;
        *(float2*)(o + 192 + 2 * lane) = f3;
    }
}

// ---------------- host launcher ----------------
extern "C" void kernel_launch(void* const* d_in, const int* in_sizes, int n_in,
                              void* d_out, int out_size) {
    const float* x    = (const float*)d_in[0];
    const int*   ei   = (const int*)d_in[1];
    const float* eatt = (const float*)d_in[2];
    const int*   ts   = (const int*)d_in[3];
    const float* Wn   = (const float*)d_in[4];
    const float* bn   = (const float*)d_in[5];
    const float* We   = (const float*)d_in[6];
    const float* be   = (const float*)d_in[7];
    const float* Temb = (const float*)d_in[8];
    const float* Wt   = (const float*)d_in[9];
    const float* bt   = (const float*)d_in[10];
    const float* Wc1  = (const float*)d_in[11];
    const float* bc1  = (const float*)d_in[12];
    const float* Wc2  = (const float*)d_in[13];
    const float* bc2  = (const float*)d_in[14];
    const float* Wr   = (const float*)d_in[15];
    const float* br   = (const float*)d_in[16];
    const float* Wm1  = (const float*)d_in[17];
    const float* bm1  = (const float*)d_in[18];
    const float* Wm2  = (const float*)d_in[19];
    const float* bm2  = (const float*)d_in[20];

    const int N = in_sizes[0] / 128;
    const int E = in_sizes[3];
    const int* src = ei;
    const int* dst = ei + E;

    float *p_xenc, *p_h, *p_x1, *p_x2, *p_res, *p_tw, *p_dinv, *p_nf;
    int *p_deg, *p_offD, *p_offS, *p_curD, *p_curS, *p_bsum, *p_srcD;
    int4* p_epk;
    cudaGetSymbolAddress((void**)&p_xenc, g_xenc);
    cudaGetSymbolAddress((void**)&p_h, g_h);
    cudaGetSymbolAddress((void**)&p_x1, g_x1);
    cudaGetSymbolAddress((void**)&p_x2, g_x2);
    cudaGetSymbolAddress((void**)&p_res, g_res);
    cudaGetSymbolAddress((void**)&p_tw, g_tw);
    cudaGetSymbolAddress((void**)&p_dinv, g_dinv);
    cudaGetSymbolAddress((void**)&p_nf, g_nf);
    cudaGetSymbolAddress((void**)&p_deg, g_deg);
    cudaGetSymbolAddress((void**)&p_offD, g_offD);
    cudaGetSymbolAddress((void**)&p_offS, g_offS);
    cudaGetSymbolAddress((void**)&p_curD, g_curD);
    cudaGetSymbolAddress((void**)&p_curS, g_curS);
    cudaGetSymbolAddress((void**)&p_bsum, g_bsum);
    cudaGetSymbolAddress((void**)&p_srcD, g_srcD);
    cudaGetSymbolAddress((void**)&p_epk, g_epk);

    int* p_indeg = p_deg;
    int* p_outdeg = p_deg + N;

    float* outp = (float*)d_out;

    const int NB = (N + 1023) / 1024;  // <=98

    cudaMemsetAsync(p_deg, 0, (size_t)2 * N * sizeof(int));

    k_hist<<<(E + 255) / 256, 256>>>(src, dst, p_indeg, p_outdeg, E);
    k_scan_blk<<<dim3(NB, 2), 1024>>>(p_indeg, p_outdeg, p_offD, p_offS, p_dinv, p_bsum, N);
    k_scan_top<<<dim3(1, 2), 128>>>(p_bsum, NB);
    k_scan_add<<<dim3(NB, 2), 1024>>>(p_offD, p_offS, p_curD, p_curS, p_bsum, N);
    k_scatter_ids<<<(E + 255) / 256, 256>>>(src, dst, ts, p_curD, p_curS, p_srcD, p_epk, E);

    k_ttable<<<1000, 64>>>(Temb, Wt, bt, p_tw);

    const int gg = (N + 127) / 128;
    const int wg = (N * 32 + 255) / 256;

    // x_enc = relu(x @ Wn + bn)
    k_gemm<128, true><<<gg, 256>>>(x, Wn, bn, nullptr, p_xenc, N);

    // conv1 h' + residual in one pass over x_enc
    k_gemm_dual<<<gg, 256>>>(p_xenc, Wc1, Wr, br, p_dinv, p_h, p_res, N);
    k_conv<<<wg, 256>>>(p_h, p_dinv, bc1, nullptr, p_offD, p_srcD, p_x1, N);

    // conv2 (+res)
    k_gemm<64, false><<<gg, 256>>>(p_x1, Wc2, nullptr, p_dinv, p_h, N);
    k_conv<<<wg, 256>>>(p_h, p_dinv, bc2, p_res, p_offD, p_srcD, p_x2, N);

    // fusion gather (edge matvec inline, We in smem, pipelined loads)
    k_fusion<<<wg, 256>>>(p_x2, p_xenc, p_tw, eatt, We, be, p_offS, p_epk, p_nf, N);

    // classifier fused with final 64->2 projection
    k_gemm_cls<<<gg, 256>>>(p_nf, Wm1, bm1, Wm2, bm2, outp, N);
}